// round 3
// baseline (speedup 1.0000x reference)
#include <cuda_runtime.h>
#include <math_constants.h>

// out = minmax_normalize( bicubic_up2x( LL[:, 0:8] ) )
// All other iqwt terms are scaled by sum(gh)=sum(fl)=sum(fh)=0 (f32 residue
// < 3e-7); the surviving sg^2 scalar cancels in the min-max normalization.
//
// Pass 1: bicubic upsample (values discarded), global min/max via encoded
//         atomicMin. Both sentinels are 0xFFFFFFFF -> one 8-byte memset node.
// Pass 2: recompute (input is L2-resident), fused normalize (1 FFMA), write.

#define THREADS 256
#define TILE_J  16            // input row-pairs per tile -> 32 output rows
#define IN_ROWS (TILE_J + 4)  // 20 input rows incl. halo
#define SMEM_W  260           // 256 cols + 2 halo each side
#define N_IN    256
#define N_OUT   512
#define N_IMG   64            // 8 batches * 8 channels (lglg slice)
#define GRID (N_IMG * 16)

// bicubic a=-0.75, src = 0.5*i - 0.25
#define WE0 (-0.03515625f)
#define WE1 ( 0.26171875f)
#define WE2 ( 0.87890625f)
#define WE3 (-0.10546875f)
#define WO0 (-0.10546875f)
#define WO1 ( 0.87890625f)
#define WO2 ( 0.26171875f)
#define WO3 (-0.03515625f)

// g_red[0] = min(enc(v)), g_red[1] = min(enc(-v)); both init to 0xFFFFFFFF.
__device__ unsigned int g_red[2];

__device__ __forceinline__ unsigned int encf(float f) {
    unsigned int u = __float_as_uint(f);
    return (u & 0x80000000u) ? ~u : (u | 0x80000000u);
}
__device__ __forceinline__ float decf(unsigned int e) {
    unsigned int u = (e & 0x80000000u) ? (e ^ 0x80000000u) : ~e;
    return __uint_as_float(u);
}

template <bool WRITE>
__global__ __launch_bounds__(THREADS)
void qwt_up_kernel(const float* __restrict__ LL, float* __restrict__ out) {
    __shared__ float s[IN_ROWS][SMEM_W];

    const int tid  = threadIdx.x;
    const int img  = blockIdx.x >> 4;        // 0..63
    const int tile = blockIdx.x & 15;        // 0..15
    const int b    = img >> 3;
    const int ch   = img & 7;                // lglg = LL channels 0..7
    const float* __restrict__ src = LL + (size_t)(b * 32 + ch) * (N_IN * N_IN);
    const int jbase = tile * TILE_J;

    float scale = 1.0f, bias = 0.0f;
    if (WRITE) {
        const float mn =  decf(g_red[0]);
        const float mx = -decf(g_red[1]);
        scale = 1.0f / (mx - mn);
        bias  = -mn * scale;
    }

    // Coalesced fill: thread tid owns input column tid; edge threads also
    // write the 2-wide replicate halo from their register value.
#pragma unroll
    for (int rr = 0; rr < IN_ROWS; rr++) {
        int gr = jbase - 2 + rr; gr = min(max(gr, 0), N_IN - 1);
        const float v = src[gr * N_IN + tid];
        s[rr][tid + 2] = v;
        if (tid == 0)          { s[rr][0]   = v; s[rr][1]   = v; }
        if (tid == N_IN - 1)   { s[rr][258] = v; s[rr][259] = v; }
    }
    __syncthreads();

    const int k = tid;
    // Rolling 5-row window of horizontal filter results.
    float he[5], ho[5];
#pragma unroll
    for (int r = 0; r < 4; r++) {
        const float z0 = s[r][k + 0], z1 = s[r][k + 1], z2 = s[r][k + 2];
        const float z3 = s[r][k + 3], z4 = s[r][k + 4];
        he[r] = WE0 * z0 + WE1 * z1 + WE2 * z2 + WE3 * z3;
        ho[r] = WO0 * z1 + WO1 * z2 + WO2 * z3 + WO3 * z4;
    }

    float lmin =  CUDART_INF_F;
    float lmax = -CUDART_INF_F;
    const size_t obase = (size_t)img * (N_OUT * N_OUT);
    const int I0 = tile * (2 * TILE_J);

#pragma unroll
    for (int jj = 0; jj < TILE_J; jj++) {
        {
            const int r = jj + 4;
            const float z0 = s[r][k + 0], z1 = s[r][k + 1], z2 = s[r][k + 2];
            const float z3 = s[r][k + 3], z4 = s[r][k + 4];
            he[4] = WE0 * z0 + WE1 * z1 + WE2 * z2 + WE3 * z3;
            ho[4] = WO0 * z1 + WO1 * z2 + WO2 * z3 + WO3 * z4;
        }
        const float ee = WE0 * he[0] + WE1 * he[1] + WE2 * he[2] + WE3 * he[3];
        const float eo = WE0 * ho[0] + WE1 * ho[1] + WE2 * ho[2] + WE3 * ho[3];
        const float oe = WO0 * he[1] + WO1 * he[2] + WO2 * he[3] + WO3 * he[4];
        const float oo = WO0 * ho[1] + WO1 * ho[2] + WO2 * ho[3] + WO3 * ho[4];

        if (WRITE) {
            const int I = I0 + 2 * jj;
            float2 v0 = make_float2(fmaf(ee, scale, bias), fmaf(eo, scale, bias));
            float2 v1 = make_float2(fmaf(oe, scale, bias), fmaf(oo, scale, bias));
            *reinterpret_cast<float2*>(out + obase + (size_t)I * N_OUT + 2 * k)       = v0;
            *reinterpret_cast<float2*>(out + obase + (size_t)(I + 1) * N_OUT + 2 * k) = v1;
        } else {
            lmin = fminf(lmin, fminf(fminf(ee, eo), fminf(oe, oo)));
            lmax = fmaxf(lmax, fmaxf(fmaxf(ee, eo), fmaxf(oe, oo)));
        }

#pragma unroll
        for (int r = 0; r < 4; r++) { he[r] = he[r + 1]; ho[r] = ho[r + 1]; }
    }

    if (!WRITE) {
#pragma unroll
        for (int off = 16; off > 0; off >>= 1) {
            lmin = fminf(lmin, __shfl_xor_sync(0xFFFFFFFFu, lmin, off));
            lmax = fmaxf(lmax, __shfl_xor_sync(0xFFFFFFFFu, lmax, off));
        }
        __shared__ float wmin[THREADS / 32], wmax[THREADS / 32];
        const int w = tid >> 5, l = tid & 31;
        if (l == 0) { wmin[w] = lmin; wmax[w] = lmax; }
        __syncthreads();
        if (tid == 0) {
            float m = wmin[0], M = wmax[0];
#pragma unroll
            for (int i = 1; i < THREADS / 32; i++) {
                m = fminf(m, wmin[i]);
                M = fmaxf(M, wmax[i]);
            }
            atomicMin(&g_red[0], encf(m));
            atomicMin(&g_red[1], encf(-M));
        }
    }
}

extern "C" void kernel_launch(void* const* d_in, const int* in_sizes, int n_in,
                              void* d_out, int out_size) {
    const float* LL = (const float*)d_in[0];
    float* out = (float*)d_out;
    (void)in_sizes; (void)n_in; (void)out_size;

    static unsigned int* red_ptr = nullptr;
    if (!red_ptr) cudaGetSymbolAddress((void**)&red_ptr, g_red);

    cudaMemsetAsync(red_ptr, 0xFF, 2 * sizeof(unsigned int));
    qwt_up_kernel<false><<<GRID, THREADS>>>(LL, out);  // min/max pass
    qwt_up_kernel<true ><<<GRID, THREADS>>>(LL, out);  // normalize + write pass
}